// round 6
// baseline (speedup 1.0000x reference)
#include <cuda_runtime.h>

#define NHID   512
#define NH16   128              // NHID floats / 4  (16-byte units per row)
#define NCLS   250
#define CHUNK  200
#define OUTW   (NCLS + CHUNK)   // 450
#define TT     32               // token tile staged in smem
#define RS     2                // row splits per class for words part
#define RPS    (CHUNK / RS)     // 100 rows per words-CTA
#define GCY    4                // row-group splits for cls part
#define MAXTOK 2048

// packed fp32x2 FMA (FFMA2) — PTX-only on sm_103a, 2x FFMA throughput
__device__ __forceinline__ void fma2(unsigned long long& acc,
                                     unsigned long long a,
                                     unsigned long long b) {
    asm("fma.rn.f32x2 %0, %1, %2, %0;" : "+l"(acc) : "l"(a), "l"(b));
}

__device__ __forceinline__ float2 u2f(unsigned long long v) {
    float2 f;
    asm("mov.b64 {%0, %1}, %2;" : "=f"(f.x), "=f"(f.y) : "l"(v));
    return f;
}

// Compute 2 rows x nb tokens (nb <= TT) of out[token, col] = W_row . x_token + b.
// Tokens blocked 4 at a time; folded-butterfly reduction: lanes 0..3 end up
// owning tokens tb..tb+3.
__device__ __forceinline__ void do_pair(
    const ulonglong2* __restrict__ wr0,   // &W[r0 * NH16/... row base, 16B units]
    const ulonglong2* __restrict__ wr1,
    const ulonglong2* __restrict__ sxu,   // smem x tile
    const int* __restrict__ s_tok,        // token ids in smem, or nullptr
    int tok_base, int nb, int lane,
    float bias0, float bias1,
    float* __restrict__ out, int col0) {
    ulonglong2 w0[4], w1[4];
#pragma unroll
    for (int j = 0; j < 4; j++) {
        w0[j] = wr0[lane + 32 * j];
        w1[j] = wr1[lane + 32 * j];
    }
    for (int tb = 0; tb < nb; tb += 4) {
        unsigned long long A[2][4][2];
#pragma unroll
        for (int r = 0; r < 2; r++)
#pragma unroll
            for (int t = 0; t < 4; t++) { A[r][t][0] = 0ull; A[r][t][1] = 0ull; }
#pragma unroll
        for (int j = 0; j < 4; j++) {
            ulonglong2 xv[4];
#pragma unroll
            for (int t = 0; t < 4; t++) {
                int tt = tb + t; tt = (tt < nb) ? tt : (nb - 1);   // pad-safe
                xv[t] = sxu[tt * NH16 + lane + 32 * j];
            }
#pragma unroll
            for (int t = 0; t < 4; t++) {
                fma2(A[0][t][0], w0[j].x, xv[t].x);
                fma2(A[0][t][1], w0[j].y, xv[t].y);
                fma2(A[1][t][0], w1[j].x, xv[t].x);
                fma2(A[1][t][1], w1[j].y, xv[t].y);
            }
        }
#pragma unroll
        for (int r = 0; r < 2; r++) {
            float s[4];
#pragma unroll
            for (int t = 0; t < 4; t++) {
                float2 f0 = u2f(A[r][t][0]);
                float2 f1 = u2f(A[r][t][1]);
                s[t] = (f0.x + f0.y) + (f1.x + f1.y);
            }
            // fold tokens (0,1) and (2,3) at xor 1
            float k01 = (lane & 1) ? s[1] : s[0];
            float g01 = (lane & 1) ? s[0] : s[1];
            k01 += __shfl_xor_sync(0xffffffffu, g01, 1);
            float k23 = (lane & 1) ? s[3] : s[2];
            float g23 = (lane & 1) ? s[2] : s[3];
            k23 += __shfl_xor_sync(0xffffffffu, g23, 1);
            // fold at xor 2: lane&3 == token index afterwards
            float e = (lane & 2) ? k23 : k01;
            float g = (lane & 2) ? k01 : k23;
            e += __shfl_xor_sync(0xffffffffu, g, 2);
            // full butterflies: same token per (lane & 3) class
            e += __shfl_xor_sync(0xffffffffu, e, 4);
            e += __shfl_xor_sync(0xffffffffu, e, 8);
            e += __shfl_xor_sync(0xffffffffu, e, 16);
            if (lane < 4 && tb + lane < nb) {
                int tg = s_tok ? s_tok[tb + lane] : (tok_base + tb + lane);
                out[(size_t)tg * OUTW + col0 + r] =
                    e + (r ? bias1 : bias0);
            }
        }
    }
}

__global__ __launch_bounds__(256)
void fused_decoder_kernel(const ulonglong2* __restrict__ xu,
                          const ulonglong2* __restrict__ Wcu,
                          const float* __restrict__ bc,
                          const ulonglong2* __restrict__ Wwu,
                          const float* __restrict__ bw,
                          const int* __restrict__ cls_raw,
                          float* __restrict__ out, int n) {
    extern __shared__ ulonglong2 sxu[];     // TT * NH16 * 16B = 64 KB
    __shared__ int s_tok[MAXTOK];
    __shared__ int s_cnt, s_not64;
    const int tid = threadIdx.x, warp = tid >> 5, lane = tid & 31;
    const int bi = blockIdx.x;

    if (bi < NCLS * RS) {
        // ---------------- words part: one class, one row-split ----------------
        const int c = bi / RS, rsplit = bi % RS;
        if (tid == 0) { s_cnt = 0; s_not64 = 0; }
        __syncthreads();
        // int32 vs int64 detection: odd int32 slots of an int64 array in
        // [0,250) are all zero; for int32 they're class values (not all zero).
        int flag = 0;
        for (int j = 2 * tid + 1; j < n; j += 512)
            if (cls_raw[j] != 0) flag = 1;
        if (flag) s_not64 = 1;
        __syncthreads();
        const int is64 = !s_not64;
        for (int i = tid; i < n; i += 256) {
            int cc = is64 ? cls_raw[2 * i] : cls_raw[i];
            if (cc == c) {
                int p = atomicAdd(&s_cnt, 1);
                if (p < MAXTOK) s_tok[p] = i;
            }
        }
        __syncthreads();
        const int cnt = min(s_cnt, MAXTOK);
        if (cnt == 0) return;

        const ulonglong2* Wu = Wwu + (size_t)c * CHUNK * NH16;
        const float* bwc = bw + (size_t)c * CHUNK;
        const int rbase = rsplit * RPS;

        for (int t0 = 0; t0 < cnt; t0 += TT) {
            const int nb = min(TT, cnt - t0);
            for (int idx = tid; idx < nb * NH16; idx += 256)
                sxu[idx] = xu[(size_t)s_tok[t0 + (idx >> 7)] * NH16 + (idx & 127)];
            __syncthreads();
            for (int rp = warp; rp < RPS / 2; rp += 8) {
                const int r0 = rbase + 2 * rp;
                do_pair(Wu + (size_t)r0 * NH16, Wu + (size_t)(r0 + 1) * NH16,
                        sxu, s_tok + t0, 0, nb, lane,
                        bwc[r0], bwc[r0 + 1], out, NCLS + r0);
            }
            __syncthreads();
        }
    } else {
        // ---------------- cls part: one token tile, one row group ----------------
        const int q = bi - NCLS * RS;
        const int tile = q >> 2;         // GCY = 4
        const int rg = q & 3;
        const int t0 = tile * TT;
        if (t0 >= n) return;
        const int nb = min(TT, n - t0);
        for (int idx = tid; idx < nb * NH16; idx += 256)
            sxu[idx] = xu[(size_t)(t0 + (idx >> 7)) * NH16 + (idx & 127)];
        __syncthreads();
        for (int rp = rg * 8 + warp; rp < NCLS / 2; rp += 32) {
            const int r0 = 2 * rp;
            do_pair(Wcu + (size_t)r0 * NH16, Wcu + (size_t)(r0 + 1) * NH16,
                    sxu, nullptr, t0, nb, lane,
                    bc[r0], bc[r0 + 1], out, r0);
        }
    }
}

extern "C" void kernel_launch(void* const* d_in, const int* in_sizes, int n_in,
                              void* d_out, int out_size) {
    const float* x  = (const float*)d_in[0];
    const float* Wc = (const float*)d_in[1];
    const float* bc = (const float*)d_in[2];
    const float* Ww = (const float*)d_in[3];
    const float* bw = (const float*)d_in[4];
    const int*   ci = (const int*)d_in[5];
    const int n = in_sizes[0] / NHID;
    float* out = (float*)d_out;

    const int smem = TT * NHID * (int)sizeof(float);   // 64 KB dynamic
    cudaFuncSetAttribute(fused_decoder_kernel,
                         cudaFuncAttributeMaxDynamicSharedMemorySize, smem);

    const int tiles = (n + TT - 1) / TT;
    const int grid = NCLS * RS + tiles * GCY;
    fused_decoder_kernel<<<grid, 256, smem>>>(
        (const ulonglong2*)x, (const ulonglong2*)Wc, bc,
        (const ulonglong2*)Ww, bw, ci, out, n);
}

// round 7
// speedup vs baseline: 1.0080x; 1.0080x over previous
#include <cuda_runtime.h>

#define NHID   512
#define NH16   128              // NHID floats / 4  (16-byte units per row)
#define NCLS   250
#define CHUNK  200
#define OUTW   (NCLS + CHUNK)   // 450
#define TT     32               // token tile staged in smem
#define RS     2                // row splits per class for words part
#define RPS    (CHUNK / RS)     // 100 rows per words-CTA
#define GCY    4                // row-group splits for cls part
#define MAXTOK 2048

// packed fp32x2 FMA (FFMA2) — PTX-only on sm_103a, 2x FFMA throughput
__device__ __forceinline__ void fma2(unsigned long long& acc,
                                     unsigned long long a,
                                     unsigned long long b) {
    asm("fma.rn.f32x2 %0, %1, %2, %0;" : "+l"(acc) : "l"(a), "l"(b));
}

__device__ __forceinline__ float2 u2f(unsigned long long v) {
    float2 f;
    asm("mov.b64 {%0, %1}, %2;" : "=f"(f.x), "=f"(f.y) : "l"(v));
    return f;
}

// Compute 2 rows x nb tokens (nb <= TT) of out[token, col] = W_row . x_token + b.
// Tokens blocked 4 at a time; folded-butterfly reduction: lanes 0..3 end up
// owning tokens tb..tb+3.
__device__ __forceinline__ void do_pair(
    const ulonglong2* __restrict__ wr0,   // &W[r0 * NH16/... row base, 16B units]
    const ulonglong2* __restrict__ wr1,
    const ulonglong2* __restrict__ sxu,   // smem x tile
    const int* __restrict__ s_tok,        // token ids in smem, or nullptr
    int tok_base, int nb, int lane,
    float bias0, float bias1,
    float* __restrict__ out, int col0) {
    ulonglong2 w0[4], w1[4];
#pragma unroll
    for (int j = 0; j < 4; j++) {
        w0[j] = wr0[lane + 32 * j];
        w1[j] = wr1[lane + 32 * j];
    }
    for (int tb = 0; tb < nb; tb += 4) {
        unsigned long long A[2][4][2];
#pragma unroll
        for (int r = 0; r < 2; r++)
#pragma unroll
            for (int t = 0; t < 4; t++) { A[r][t][0] = 0ull; A[r][t][1] = 0ull; }
#pragma unroll
        for (int j = 0; j < 4; j++) {
            ulonglong2 xv[4];
#pragma unroll
            for (int t = 0; t < 4; t++) {
                int tt = tb + t; tt = (tt < nb) ? tt : (nb - 1);   // pad-safe
                xv[t] = sxu[tt * NH16 + lane + 32 * j];
            }
#pragma unroll
            for (int t = 0; t < 4; t++) {
                fma2(A[0][t][0], w0[j].x, xv[t].x);
                fma2(A[0][t][1], w0[j].y, xv[t].y);
                fma2(A[1][t][0], w1[j].x, xv[t].x);
                fma2(A[1][t][1], w1[j].y, xv[t].y);
            }
        }
#pragma unroll
        for (int r = 0; r < 2; r++) {
            float s[4];
#pragma unroll
            for (int t = 0; t < 4; t++) {
                float2 f0 = u2f(A[r][t][0]);
                float2 f1 = u2f(A[r][t][1]);
                s[t] = (f0.x + f0.y) + (f1.x + f1.y);
            }
            // fold tokens (0,1) and (2,3) at xor 1
            float k01 = (lane & 1) ? s[1] : s[0];
            float g01 = (lane & 1) ? s[0] : s[1];
            k01 += __shfl_xor_sync(0xffffffffu, g01, 1);
            float k23 = (lane & 1) ? s[3] : s[2];
            float g23 = (lane & 1) ? s[2] : s[3];
            k23 += __shfl_xor_sync(0xffffffffu, g23, 1);
            // fold at xor 2: lane&3 == token index afterwards
            float e = (lane & 2) ? k23 : k01;
            float g = (lane & 2) ? k01 : k23;
            e += __shfl_xor_sync(0xffffffffu, g, 2);
            // full butterflies: same token per (lane & 3) class
            e += __shfl_xor_sync(0xffffffffu, e, 4);
            e += __shfl_xor_sync(0xffffffffu, e, 8);
            e += __shfl_xor_sync(0xffffffffu, e, 16);
            if (lane < 4 && tb + lane < nb) {
                int tg = s_tok ? s_tok[tb + lane] : (tok_base + tb + lane);
                out[(size_t)tg * OUTW + col0 + r] =
                    e + (r ? bias1 : bias0);
            }
        }
    }
}

__global__ __launch_bounds__(256)
void fused_decoder_kernel(const ulonglong2* __restrict__ xu,
                          const ulonglong2* __restrict__ Wcu,
                          const float* __restrict__ bc,
                          const ulonglong2* __restrict__ Wwu,
                          const float* __restrict__ bw,
                          const int* __restrict__ cls_raw,
                          float* __restrict__ out, int n) {
    extern __shared__ ulonglong2 sxu[];     // TT * NH16 * 16B = 64 KB
    __shared__ int s_tok[MAXTOK];
    __shared__ int s_cnt, s_not64;
    const int tid = threadIdx.x, warp = tid >> 5, lane = tid & 31;
    const int bi = blockIdx.x;

    if (bi < NCLS * RS) {
        // ---------------- words part: one class, one row-split ----------------
        const int c = bi / RS, rsplit = bi % RS;
        if (tid == 0) { s_cnt = 0; s_not64 = 0; }
        __syncthreads();
        // int32 vs int64 detection: odd int32 slots of an int64 array in
        // [0,250) are all zero; for int32 they're class values (not all zero).
        int flag = 0;
        for (int j = 2 * tid + 1; j < n; j += 512)
            if (cls_raw[j] != 0) flag = 1;
        if (flag) s_not64 = 1;
        __syncthreads();
        const int is64 = !s_not64;
        for (int i = tid; i < n; i += 256) {
            int cc = is64 ? cls_raw[2 * i] : cls_raw[i];
            if (cc == c) {
                int p = atomicAdd(&s_cnt, 1);
                if (p < MAXTOK) s_tok[p] = i;
            }
        }
        __syncthreads();
        const int cnt = min(s_cnt, MAXTOK);
        if (cnt == 0) return;

        const ulonglong2* Wu = Wwu + (size_t)c * CHUNK * NH16;
        const float* bwc = bw + (size_t)c * CHUNK;
        const int rbase = rsplit * RPS;

        for (int t0 = 0; t0 < cnt; t0 += TT) {
            const int nb = min(TT, cnt - t0);
            for (int idx = tid; idx < nb * NH16; idx += 256)
                sxu[idx] = xu[(size_t)s_tok[t0 + (idx >> 7)] * NH16 + (idx & 127)];
            __syncthreads();
            for (int rp = warp; rp < RPS / 2; rp += 8) {
                const int r0 = rbase + 2 * rp;
                do_pair(Wu + (size_t)r0 * NH16, Wu + (size_t)(r0 + 1) * NH16,
                        sxu, s_tok + t0, 0, nb, lane,
                        bwc[r0], bwc[r0 + 1], out, NCLS + r0);
            }
            __syncthreads();
        }
    } else {
        // ---------------- cls part: one token tile, one row group ----------------
        const int q = bi - NCLS * RS;
        const int tile = q >> 2;         // GCY = 4
        const int rg = q & 3;
        const int t0 = tile * TT;
        if (t0 >= n) return;
        const int nb = min(TT, n - t0);
        for (int idx = tid; idx < nb * NH16; idx += 256)
            sxu[idx] = xu[(size_t)(t0 + (idx >> 7)) * NH16 + (idx & 127)];
        __syncthreads();
        for (int rp = rg * 8 + warp; rp < NCLS / 2; rp += 32) {
            const int r0 = 2 * rp;
            do_pair(Wcu + (size_t)r0 * NH16, Wcu + (size_t)(r0 + 1) * NH16,
                    sxu, nullptr, t0, nb, lane,
                    bc[r0], bc[r0 + 1], out, r0);
        }
    }
}

extern "C" void kernel_launch(void* const* d_in, const int* in_sizes, int n_in,
                              void* d_out, int out_size) {
    const float* x  = (const float*)d_in[0];
    const float* Wc = (const float*)d_in[1];
    const float* bc = (const float*)d_in[2];
    const float* Ww = (const float*)d_in[3];
    const float* bw = (const float*)d_in[4];
    const int*   ci = (const int*)d_in[5];
    const int n = in_sizes[0] / NHID;
    float* out = (float*)d_out;

    const int smem = TT * NHID * (int)sizeof(float);   // 64 KB dynamic
    cudaFuncSetAttribute(fused_decoder_kernel,
                         cudaFuncAttributeMaxDynamicSharedMemorySize, smem);

    const int tiles = (n + TT - 1) / TT;
    const int grid = NCLS * RS + tiles * GCY;
    fused_decoder_kernel<<<grid, 256, smem>>>(
        (const ulonglong2*)x, (const ulonglong2*)Wc, bc,
        (const ulonglong2*)Ww, bw, ci, out, n);
}